// round 8
// baseline (speedup 1.0000x reference)
#include <cuda_runtime.h>
#include <cuda_bf16.h>
#include <math.h>
#include <stdint.h>

#define NLEV   16
#define TBITS  20
#define TSZ    (1u << TBITS)
#define TMASK  (TSZ - 1u)
#define PRIME  2654435761u

#define CTA    128          // 4 warps, 32 rows each
#define TILE   128

#define W1S 80      // W1^T row stride (bytes): 32 bf16 padded to 80
#define W2S 272     // W2^T row stride: 128 bf16 padded to 272
#define XS  80      // X row stride: 32 bf16 padded to 80

#define OFF_W1T 0
#define OFF_W2T 10240
#define OFF_X   45056
#define OFF_B1  55296
#define OFF_B2  55808
#define OFF_W3  56320
#define OFF_B3  57856
#define DSMEM   57984       // x3 CTAs = 174KB < 228KB

__device__ __forceinline__ uint32_t smem_u32(const void* p) {
    uint32_t a;
    asm("{ .reg .u64 t; cvta.to.shared.u64 t, %1; cvt.u32.u64 %0, t; }"
        : "=r"(a) : "l"(p));
    return a;
}
__device__ __forceinline__ uint32_t pack_bf16x2(float lo, float hi) {
    __nv_bfloat162 v = __float22bfloat162_rn(make_float2(lo, hi));
    return *(uint32_t*)&v;
}
__device__ __forceinline__ void ldm_x4(uint32_t* r, uint32_t addr) {
    asm volatile("ldmatrix.sync.aligned.m8n8.x4.shared.b16 {%0,%1,%2,%3}, [%4];"
                 : "=r"(r[0]), "=r"(r[1]), "=r"(r[2]), "=r"(r[3]) : "r"(addr));
}
__device__ __forceinline__ void mma16816(float* d, const uint32_t* a, const uint32_t* b) {
    asm volatile(
        "mma.sync.aligned.m16n8k16.row.col.f32.bf16.bf16.f32 "
        "{%0,%1,%2,%3}, {%4,%5,%6,%7}, {%8,%9}, {%0,%1,%2,%3};"
        : "+f"(d[0]), "+f"(d[1]), "+f"(d[2]), "+f"(d[3])
        : "r"(a[0]), "r"(a[1]), "r"(a[2]), "r"(a[3]), "r"(b[0]), "r"(b[1]));
}

__global__ __launch_bounds__(CTA, 3)
void ngp_mma4_kernel(const float2* __restrict__ uv, const float* __restrict__ tables,
                     const float* __restrict__ w1, const float* __restrict__ b1,
                     const float* __restrict__ w2, const float* __restrict__ b2,
                     const float* __restrict__ w3, const float* __restrict__ b3,
                     float* __restrict__ out, int n)
{
    extern __shared__ char smem[];
    const int tid  = threadIdx.x;
    const int wid  = tid >> 5;          // 0..3
    const int lane = tid & 31;
    const int q    = lane >> 2;
    const int c    = lane & 3;

    // ---- stage weights once per persistent CTA ----
    for (int idx = tid; idx < 32 * 128; idx += CTA) {     // W1^T [n=128][k=32]
        int j = idx >> 5, k = idx & 31;
        *(__nv_bfloat16*)(smem + OFF_W1T + j * W1S + k * 2) = __float2bfloat16(w1[k * 128 + j]);
    }
    for (int idx = tid; idx < 128 * 128; idx += CTA) {    // W2^T [n=128][k=128]
        int j = idx >> 7, k = idx & 127;
        *(__nv_bfloat16*)(smem + OFF_W2T + j * W2S + k * 2) = __float2bfloat16(w2[k * 128 + j]);
    }
    float* sb1 = (float*)(smem + OFF_B1);
    float* sb2 = (float*)(smem + OFF_B2);
    float* sw3 = (float*)(smem + OFF_W3);
    float* sb3 = (float*)(smem + OFF_B3);
    for (int i = tid; i < 128; i += CTA) { sb1[i] = b1[i]; sb2[i] = b2[i]; }
    for (int i = tid; i < 384; i += CTA) sw3[i] = w3[i];
    if (tid < 3) sb3[tid] = b3[tid];
    __syncthreads();        // only CTA-wide sync; X is warp-private below

    const uint32_t sW1 = smem_u32(smem + OFF_W1T);
    const uint32_t sW2 = smem_u32(smem + OFF_W2T);
    const uint32_t sX  = smem_u32(smem + OFF_X);
    char* Xbuf = smem + OFF_X;

    // ldmatrix lane-constant address parts (layout validated R5-R7)
    const int rbase = wid * 32 + (lane & 7) + ((lane >> 3) & 1) * 8;
    const uint32_t offA  = (uint32_t)(rbase * XS) + ((lane >> 4) * 16);
    const uint32_t offB1 = (uint32_t)((lane & 7) * W1S) + ((lane >> 3) * 16);
    const uint32_t offB2 = (uint32_t)((lane & 7) * W2S) + ((lane >> 3) * 16);

    // corner-parallel encode: lane = 4*psub + corner
    const int corner = lane & 3;
    const int psub   = lane >> 2;
    const int ox     = corner >> 1;
    const int oy     = corner & 1;

    const int ntiles = (n + TILE - 1) / TILE;
    for (int t = blockIdx.x; t < ntiles; t += gridDim.x) {

        // ========== encode 32 points/warp: 4 groups of 8, 4 lanes/point ==========
        __syncwarp();
#pragma unroll
        for (int g = 0; g < 4; g++) {
            const int pt  = wid * 32 + g * 8 + psub;
            const int gid = t * TILE + pt;
            const float2 p = __ldg(&uv[gid < n ? gid : (n - 1)]);
#pragma unroll
            for (int l = 0; l < NLEV; l++) {
                const unsigned res = 16u << l;
                float px = p.x * (float)res, py = p.y * (float)res;
                float fx = floorf(px), fy = floorf(py);
                float wx = px - fx, wy = py - fy;
                unsigned cx = (unsigned)(int)fx + (unsigned)ox;
                unsigned cy = (unsigned)(int)fy + (unsigned)oy;
                unsigned idx;
                if (res <= 512u)
                    idx = cx + cy * (res + 1u);
                else
                    idx = (cx ^ (cy * PRIME)) & TMASK;
                float2 f = __ldg((const float2*)tables + (size_t)l * TSZ + idx);
                float w = (ox ? wx : 1.f - wx) * (oy ? wy : 1.f - wy);
                float v0 = w * f.x, v1 = w * f.y;
                v0 += __shfl_xor_sync(0xffffffffu, v0, 1);
                v1 += __shfl_xor_sync(0xffffffffu, v1, 1);
                v0 += __shfl_xor_sync(0xffffffffu, v0, 2);
                v1 += __shfl_xor_sync(0xffffffffu, v1, 2);
                if (corner == 0)
                    *(uint32_t*)(Xbuf + pt * XS + l * 4) = pack_bf16x2(v0, v1);
            }
        }
        __syncwarp();

        // ========== layer 1: 32 rows/warp (2 m-tiles), B-frags shared ==========
        uint32_t xa[2][2][4];
#pragma unroll
        for (int mt = 0; mt < 2; mt++) {
            ldm_x4(xa[mt][0], sX + offA + mt * (16 * XS));
            ldm_x4(xa[mt][1], sX + offA + mt * (16 * XS) + 32);
        }

        uint32_t ha[2][8][4];   // register-resident H for both m-tiles
#pragma unroll
        for (int s = 0; s < 4; s++) {
#pragma unroll
            for (int nt = 0; nt < 4; nt++) {
                const int col0 = s * 32 + nt * 8;
                uint32_t bf[4];
                ldm_x4(bf, sW1 + (uint32_t)(col0 * W1S) + offB1);
                float2 bb = *(const float2*)(sb1 + col0 + 2 * c);
                const int K = 2 * s + (nt >> 1);
#pragma unroll
                for (int mt = 0; mt < 2; mt++) {
                    float d[4] = {0.f, 0.f, 0.f, 0.f};
                    mma16816(d, xa[mt][0], bf);
                    mma16816(d, xa[mt][1], bf + 2);
                    float h0 = fmaxf(d[0] + bb.x, 0.f);
                    float h1 = fmaxf(d[1] + bb.y, 0.f);
                    float h2 = fmaxf(d[2] + bb.x, 0.f);
                    float h3 = fmaxf(d[3] + bb.y, 0.f);
                    if (nt & 1) { ha[mt][K][2] = pack_bf16x2(h0, h1); ha[mt][K][3] = pack_bf16x2(h2, h3); }
                    else        { ha[mt][K][0] = pack_bf16x2(h0, h1); ha[mt][K][1] = pack_bf16x2(h2, h3); }
                }
            }
        }

        // ===== layer 2 (H @ W2) + layer 3, B-frags shared across 2 m-tiles =====
        float o[2][6] = {};       // [mt][row q: 0..2, row q+8: 3..5]
#pragma unroll
        for (int s = 0; s < 4; s++) {
#pragma unroll
            for (int nt = 0; nt < 4; nt++) {
                const int col0 = s * 32 + nt * 8;
                float d[2][4] = {};
#pragma unroll
                for (int ktp = 0; ktp < 4; ktp++) {
                    uint32_t bf[4];
                    ldm_x4(bf, sW2 + (uint32_t)(col0 * W2S) + ktp * 64 + offB2);
#pragma unroll
                    for (int mt = 0; mt < 2; mt++) {
                        mma16816(d[mt], ha[mt][2 * ktp],     bf);
                        mma16816(d[mt], ha[mt][2 * ktp + 1], bf + 2);
                    }
                }
                float2 bb = *(const float2*)(sb2 + col0 + 2 * c);
                const float* w3a = sw3 + 3 * (col0 + 2 * c);
                const float* w3b = w3a + 3;
#pragma unroll
                for (int mt = 0; mt < 2; mt++) {
                    float h0 = fmaxf(d[mt][0] + bb.x, 0.f);
                    float h1 = fmaxf(d[mt][1] + bb.y, 0.f);
                    float h2 = fmaxf(d[mt][2] + bb.x, 0.f);
                    float h3 = fmaxf(d[mt][3] + bb.y, 0.f);
                    o[mt][0] = fmaf(h0, w3a[0], fmaf(h1, w3b[0], o[mt][0]));
                    o[mt][1] = fmaf(h0, w3a[1], fmaf(h1, w3b[1], o[mt][1]));
                    o[mt][2] = fmaf(h0, w3a[2], fmaf(h1, w3b[2], o[mt][2]));
                    o[mt][3] = fmaf(h2, w3a[0], fmaf(h3, w3b[0], o[mt][3]));
                    o[mt][4] = fmaf(h2, w3a[1], fmaf(h3, w3b[1], o[mt][4]));
                    o[mt][5] = fmaf(h2, w3a[2], fmaf(h3, w3b[2], o[mt][5]));
                }
            }
        }

        // quad reduction across cpair lanes
#pragma unroll
        for (int mt = 0; mt < 2; mt++)
#pragma unroll
            for (int v = 0; v < 6; v++) {
                float x = o[mt][v];
                x += __shfl_xor_sync(0xffffffffu, x, 1);
                x += __shfl_xor_sync(0xffffffffu, x, 2);
                o[mt][v] = x;
            }

        if (c == 0) {
#pragma unroll
            for (int mt = 0; mt < 2; mt++) {
                int row0 = t * TILE + wid * 32 + mt * 16 + q;
                int row1 = row0 + 8;
                if (row0 < n) {
                    out[3 * row0 + 0] = 1.f / (1.f + __expf(-(o[mt][0] + sb3[0])));
                    out[3 * row0 + 1] = 1.f / (1.f + __expf(-(o[mt][1] + sb3[1])));
                    out[3 * row0 + 2] = 1.f / (1.f + __expf(-(o[mt][2] + sb3[2])));
                }
                if (row1 < n) {
                    out[3 * row1 + 0] = 1.f / (1.f + __expf(-(o[mt][3] + sb3[0])));
                    out[3 * row1 + 1] = 1.f / (1.f + __expf(-(o[mt][4] + sb3[1])));
                    out[3 * row1 + 2] = 1.f / (1.f + __expf(-(o[mt][5] + sb3[2])));
                }
            }
        }
    }
}

extern "C" void kernel_launch(void* const* d_in, const int* in_sizes, int n_in,
                              void* d_out, int out_size)
{
    const float2* uv     = (const float2*)d_in[0];
    const float*  tables = (const float*) d_in[1];
    const float*  w1     = (const float*) d_in[2];
    const float*  b1     = (const float*) d_in[3];
    const float*  w2     = (const float*) d_in[4];
    const float*  b2     = (const float*) d_in[5];
    const float*  w3     = (const float*) d_in[6];
    const float*  b3     = (const float*) d_in[7];
    float* out = (float*)d_out;

    int n = in_sizes[0] / 2;
    int ntiles = (n + TILE - 1) / TILE;

    cudaFuncSetAttribute(ngp_mma4_kernel,
                         cudaFuncAttributeMaxDynamicSharedMemorySize, DSMEM);

    int grid = 456;                 // 3 persistent CTAs / SM (152 SMs)
    if (grid > ntiles) grid = ntiles;

    ngp_mma4_kernel<<<grid, CTA, DSMEM>>>(uv, tables, w1, b1, w2, b2, w3, b3, out, n);
}

// round 9
// speedup vs baseline: 1.1780x; 1.1780x over previous
#include <cuda_runtime.h>
#include <cuda_bf16.h>
#include <math.h>
#include <stdint.h>

#define NLEV   16
#define TBITS  20
#define TSZ    (1u << TBITS)
#define TMASK  (TSZ - 1u)
#define PRIME  2654435761u

#define CTA    256
#define TILE   128

#define W1S 80      // W1^T row stride (bytes): 32 bf16 padded
#define W2S8 144    // W2^T fp8 row stride: 128 B + 16 pad
#define XS  80      // X row stride: 32 bf16 padded

#define OFF_W1T 0
#define OFF_W28 10240
#define OFF_X   28672
#define OFF_B1  38912
#define OFF_B2  39424
#define OFF_W3  39936
#define OFF_B3  41472
#define DSMEM   41600

#define SC     4096.0f
#define INV_SC (1.0f / 4096.0f)

__device__ __forceinline__ uint32_t smem_u32(const void* p) {
    uint32_t a;
    asm("{ .reg .u64 t; cvta.to.shared.u64 t, %1; cvt.u32.u64 %0, t; }"
        : "=r"(a) : "l"(p));
    return a;
}
__device__ __forceinline__ uint32_t pack_bf16x2(float lo, float hi) {
    __nv_bfloat162 v = __float22bfloat162_rn(make_float2(lo, hi));
    return *(uint32_t*)&v;
}
// pack two floats to e4m3 pair: byte0 = lo, byte1 = hi
__device__ __forceinline__ unsigned short pack_e4m3x2(float lo, float hi) {
    unsigned short r;
    asm("cvt.rn.satfinite.e4m3x2.f32 %0, %1, %2;" : "=h"(r) : "f"(hi), "f"(lo));
    return r;
}
__device__ __forceinline__ void ldm_x4(uint32_t* r, uint32_t addr) {
    asm volatile("ldmatrix.sync.aligned.m8n8.x4.shared.b16 {%0,%1,%2,%3}, [%4];"
                 : "=r"(r[0]), "=r"(r[1]), "=r"(r[2]), "=r"(r[3]) : "r"(addr));
}
__device__ __forceinline__ void mma16816(float* d, const uint32_t* a, const uint32_t* b) {
    asm volatile(
        "mma.sync.aligned.m16n8k16.row.col.f32.bf16.bf16.f32 "
        "{%0,%1,%2,%3}, {%4,%5,%6,%7}, {%8,%9}, {%0,%1,%2,%3};"
        : "+f"(d[0]), "+f"(d[1]), "+f"(d[2]), "+f"(d[3])
        : "r"(a[0]), "r"(a[1]), "r"(a[2]), "r"(a[3]), "r"(b[0]), "r"(b[1]));
}
__device__ __forceinline__ void mma16832_fp8(float* d, const uint32_t* a, const uint32_t* b) {
    asm volatile(
        "mma.sync.aligned.m16n8k32.row.col.f32.e4m3.e4m3.f32 "
        "{%0,%1,%2,%3}, {%4,%5,%6,%7}, {%8,%9}, {%0,%1,%2,%3};"
        : "+f"(d[0]), "+f"(d[1]), "+f"(d[2]), "+f"(d[3])
        : "r"(a[0]), "r"(a[1]), "r"(a[2]), "r"(a[3]), "r"(b[0]), "r"(b[1]));
}

__global__ __launch_bounds__(CTA, 2)
void ngp_fp8_kernel(const float2* __restrict__ uv, const float* __restrict__ tables,
                    const float* __restrict__ w1, const float* __restrict__ b1,
                    const float* __restrict__ w2, const float* __restrict__ b2,
                    const float* __restrict__ w3, const float* __restrict__ b3,
                    float* __restrict__ out, int n)
{
    extern __shared__ char smem[];
    const int tid  = threadIdx.x;
    const int wid  = tid >> 5;
    const int lane = tid & 31;
    const int q    = lane >> 2;
    const int c    = lane & 3;

    // ---- stage weights once per persistent CTA ----
    for (int idx = tid; idx < 32 * 128; idx += CTA) {      // W1^T [n][k] bf16
        int j = idx >> 5, k = idx & 31;
        *(__nv_bfloat16*)(smem + OFF_W1T + j * W1S + k * 2) = __float2bfloat16(w1[k * 128 + j]);
    }
    for (int idx = tid; idx < 128 * 128; idx += CTA) {     // W2^T [n][k] e4m3
        int j = idx >> 7, k = idx & 127;
        unsigned short p = pack_e4m3x2(w2[k * 128 + j], 0.f);
        *(unsigned char*)(smem + OFF_W28 + j * W2S8 + k) = (unsigned char)(p & 0xFF);
    }
    float* sb1 = (float*)(smem + OFF_B1);
    float* sb2 = (float*)(smem + OFF_B2);
    float* sw3 = (float*)(smem + OFF_W3);
    float* sb3 = (float*)(smem + OFF_B3);
    for (int i = tid; i < 128; i += CTA) { sb1[i] = b1[i]; sb2[i] = b2[i] * SC; }
    for (int i = tid; i < 384; i += CTA) sw3[i] = w3[i];
    if (tid < 3) sb3[tid] = b3[tid];
    __syncthreads();   // only CTA-wide sync; X is warp-private below

    const uint32_t sW1 = smem_u32(smem + OFF_W1T);
    const uint32_t sW28 = smem_u32(smem + OFF_W28);
    const uint32_t sX  = smem_u32(smem + OFF_X);
    char* Xbuf = smem + OFF_X;

    // ldmatrix lane-constant address parts (layout validated R5-R7)
    const int rA = wid * 16 + (lane & 7) + ((lane >> 3) & 1) * 8;
    const uint32_t offA   = (uint32_t)(rA * XS) + ((lane >> 4) * 16);
    const uint32_t offB1  = (uint32_t)((lane & 7) * W1S) + ((lane >> 3) * 16);
    const uint32_t offB28 = (uint32_t)((lane & 7) * W2S8) + ((lane >> 3) * 16);

    // corner-parallel encode: lane = 4*psub + corner
    const int corner = lane & 3;
    const int psub   = lane >> 2;
    const int ox     = corner >> 1;
    const int oy     = corner & 1;

    const int ntiles = (n + TILE - 1) / TILE;
    for (int t = blockIdx.x; t < ntiles; t += gridDim.x) {

        // ============ encode 16 points/warp: 2 groups of 8, 4 lanes/point ============
        __syncwarp();
#pragma unroll
        for (int g = 0; g < 2; g++) {
            const int pt  = wid * 16 + g * 8 + psub;
            const int gid = t * TILE + pt;
            const float2 p = __ldg(&uv[gid < n ? gid : (n - 1)]);
#pragma unroll
            for (int l = 0; l < NLEV; l++) {
                const unsigned res = 16u << l;
                float px = p.x * (float)res, py = p.y * (float)res;
                float fx = floorf(px), fy = floorf(py);
                float wx = px - fx, wy = py - fy;
                unsigned cx = (unsigned)(int)fx + (unsigned)ox;
                unsigned cy = (unsigned)(int)fy + (unsigned)oy;
                unsigned idx;
                if (res <= 512u)
                    idx = cx + cy * (res + 1u);
                else
                    idx = (cx ^ (cy * PRIME)) & TMASK;
                float2 f = __ldg((const float2*)tables + (size_t)l * TSZ + idx);
                float w = (ox ? wx : 1.f - wx) * (oy ? wy : 1.f - wy);
                float v0 = w * f.x, v1 = w * f.y;
                v0 += __shfl_xor_sync(0xffffffffu, v0, 1);
                v1 += __shfl_xor_sync(0xffffffffu, v1, 1);
                v0 += __shfl_xor_sync(0xffffffffu, v0, 2);
                v1 += __shfl_xor_sync(0xffffffffu, v1, 2);
                if (corner == 0)
                    *(uint32_t*)(Xbuf + pt * XS + l * 4) = pack_bf16x2(v0, v1);
            }
        }
        __syncwarp();

        // ========== layer 1 (bf16): 16 rows/warp; H -> fp8 A-fragments ==========
        uint32_t xa[2][4];
        ldm_x4(xa[0], sX + offA);
        ldm_x4(xa[1], sX + offA + 32);

        uint32_t ha8[4][4];          // layer-2 fp8 A fragments (4 k32-steps)
        unsigned short plo_prev = 0, phi_prev = 0;
#pragma unroll
        for (int s = 0; s < 4; s++) {
#pragma unroll
            for (int nt = 0; nt < 4; nt++) {
                const int b = 4 * s + nt;          // 8-col block index 0..15
                const int col0 = 8 * b;
                uint32_t bf[4];
                ldm_x4(bf, sW1 + (uint32_t)(col0 * W1S) + offB1);
                float d[4] = {0.f, 0.f, 0.f, 0.f};
                mma16816(d, xa[0], bf);
                mma16816(d, xa[1], bf + 2);
                float2 bb = *(const float2*)(sb1 + col0 + 2 * c);
                float h0 = fmaxf(d[0] + bb.x, 0.f) * SC;   // row q,   col 2c
                float h1 = fmaxf(d[1] + bb.y, 0.f) * SC;   // row q,   col 2c+1
                float h2 = fmaxf(d[2] + bb.x, 0.f) * SC;   // row q+8, col 2c
                float h3 = fmaxf(d[3] + bb.y, 0.f) * SC;   // row q+8, col 2c+1
                unsigned short plo = pack_e4m3x2(h0, h1);
                unsigned short phi = pack_e4m3x2(h2, h3);
                if ((b & 1) == 0) {
                    plo_prev = plo; phi_prev = phi;
                } else {
                    uint32_t u = (uint32_t)plo_prev | ((uint32_t)plo << 16);
                    uint32_t w = (uint32_t)phi_prev | ((uint32_t)phi << 16);
                    int s0 = (lane & ~3) | (2 * (c & 1));
                    uint32_t u0 = __shfl_sync(0xffffffffu, u, s0);
                    uint32_t u1 = __shfl_sync(0xffffffffu, u, s0 + 1);
                    uint32_t w0 = __shfl_sync(0xffffffffu, w, s0);
                    uint32_t w1r = __shfl_sync(0xffffffffu, w, s0 + 1);
                    uint32_t sel = (c < 2) ? 0x5410u : 0x7632u;
                    int j = b >> 1, kk = j >> 1, half = j & 1;
                    ha8[kk][2 * half + 0] = __byte_perm(u0, u1, sel);  // a0 / a2 (row q)
                    ha8[kk][2 * half + 1] = __byte_perm(w0, w1r, sel); // a1 / a3 (row q+8)
                }
            }
        }

        // ===== layer 2 (fp8, k=32/mma) fused with layer 3 accumulation =====
        float o[6] = {};
#pragma unroll
        for (int s = 0; s < 4; s++) {
#pragma unroll
            for (int nt = 0; nt < 4; nt++) {
                const int col0 = s * 32 + nt * 8;
                float d[4] = {0.f, 0.f, 0.f, 0.f};
#pragma unroll
                for (int kk2 = 0; kk2 < 2; kk2++) {
                    uint32_t bf[4];
                    ldm_x4(bf, sW28 + (uint32_t)(col0 * W2S8) + kk2 * 64 + offB28);
                    mma16832_fp8(d, ha8[2 * kk2],     bf);
                    mma16832_fp8(d, ha8[2 * kk2 + 1], bf + 2);
                }
                float2 bb = *(const float2*)(sb2 + col0 + 2 * c);
                float h0 = fmaxf(d[0] + bb.x, 0.f);
                float h1 = fmaxf(d[1] + bb.y, 0.f);
                float h2 = fmaxf(d[2] + bb.x, 0.f);
                float h3 = fmaxf(d[3] + bb.y, 0.f);
                const float* w3a = sw3 + 3 * (col0 + 2 * c);
                const float* w3b = w3a + 3;
                o[0] = fmaf(h0, w3a[0], fmaf(h1, w3b[0], o[0]));
                o[1] = fmaf(h0, w3a[1], fmaf(h1, w3b[1], o[1]));
                o[2] = fmaf(h0, w3a[2], fmaf(h1, w3b[2], o[2]));
                o[3] = fmaf(h2, w3a[0], fmaf(h3, w3b[0], o[3]));
                o[4] = fmaf(h2, w3a[1], fmaf(h3, w3b[1], o[4]));
                o[5] = fmaf(h2, w3a[2], fmaf(h3, w3b[2], o[5]));
            }
        }

        // quad reduction, unscale, sigmoid, store
#pragma unroll
        for (int v = 0; v < 6; v++) {
            float x = o[v];
            x += __shfl_xor_sync(0xffffffffu, x, 1);
            x += __shfl_xor_sync(0xffffffffu, x, 2);
            o[v] = x * INV_SC;
        }

        if (c == 0) {
            int row0 = t * TILE + wid * 16 + q;
            int row1 = row0 + 8;
            if (row0 < n) {
                out[3 * row0 + 0] = 1.f / (1.f + __expf(-(o[0] + sb3[0])));
                out[3 * row0 + 1] = 1.f / (1.f + __expf(-(o[1] + sb3[1])));
                out[3 * row0 + 2] = 1.f / (1.f + __expf(-(o[2] + sb3[2])));
            }
            if (row1 < n) {
                out[3 * row1 + 0] = 1.f / (1.f + __expf(-(o[3] + sb3[0])));
                out[3 * row1 + 1] = 1.f / (1.f + __expf(-(o[4] + sb3[1])));
                out[3 * row1 + 2] = 1.f / (1.f + __expf(-(o[5] + sb3[2])));
            }
        }
    }
}

extern "C" void kernel_launch(void* const* d_in, const int* in_sizes, int n_in,
                              void* d_out, int out_size)
{
    const float2* uv     = (const float2*)d_in[0];
    const float*  tables = (const float*) d_in[1];
    const float*  w1     = (const float*) d_in[2];
    const float*  b1     = (const float*) d_in[3];
    const float*  w2     = (const float*) d_in[4];
    const float*  b2     = (const float*) d_in[5];
    const float*  w3     = (const float*) d_in[6];
    const float*  b3     = (const float*) d_in[7];
    float* out = (float*)d_out;

    int n = in_sizes[0] / 2;
    int ntiles = (n + TILE - 1) / TILE;

    cudaFuncSetAttribute(ngp_fp8_kernel,
                         cudaFuncAttributeMaxDynamicSharedMemorySize, DSMEM);

    int grid = 304;                 // 2 persistent CTAs / SM
    if (grid > ntiles) grid = ntiles;

    ngp_fp8_kernel<<<grid, CTA, DSMEM>>>(uv, tables, w1, b1, w2, b2, w3, b3, out, n);
}

// round 10
// speedup vs baseline: 1.2502x; 1.0612x over previous
#include <cuda_runtime.h>
#include <cuda_bf16.h>
#include <math.h>
#include <stdint.h>

#define NLEV   16
#define TBITS  20
#define TSZ    (1u << TBITS)
#define TMASK  (TSZ - 1u)
#define PRIME  2654435761u

#define CTA    256
#define TILE   128

#define W1S 80      // W1^T row stride (bytes): 32 bf16 padded
#define W2S8 144    // W2^T fp8 row stride: 128 B + 16 pad
#define XS  80      // X row stride: 32 bf16 padded

#define OFF_W1T 0
#define OFF_W28 10240
#define OFF_X   28672
#define OFF_B1  38912
#define OFF_B2  39424
#define OFF_W3  39936
#define OFF_B3  41472
#define DSMEM   41600

#define SC     4096.0f
#define INV_SC (1.0f / 4096.0f)

__device__ __forceinline__ uint32_t smem_u32(const void* p) {
    uint32_t a;
    asm("{ .reg .u64 t; cvta.to.shared.u64 t, %1; cvt.u32.u64 %0, t; }"
        : "=r"(a) : "l"(p));
    return a;
}
__device__ __forceinline__ uint32_t pack_bf16x2(float lo, float hi) {
    __nv_bfloat162 v = __float22bfloat162_rn(make_float2(lo, hi));
    return *(uint32_t*)&v;
}
// pack two floats to e4m3 pair: byte0 = lo, byte1 = hi (same helper validated in R9)
__device__ __forceinline__ unsigned short pack_e4m3x2(float lo, float hi) {
    unsigned short r;
    asm("cvt.rn.satfinite.e4m3x2.f32 %0, %1, %2;" : "=h"(r) : "f"(hi), "f"(lo));
    return r;
}
__device__ __forceinline__ void ldm_x4(uint32_t* r, uint32_t addr) {
    asm volatile("ldmatrix.sync.aligned.m8n8.x4.shared.b16 {%0,%1,%2,%3}, [%4];"
                 : "=r"(r[0]), "=r"(r[1]), "=r"(r[2]), "=r"(r[3]) : "r"(addr));
}
__device__ __forceinline__ void mma16816(float* d, const uint32_t* a, const uint32_t* b) {
    asm volatile(
        "mma.sync.aligned.m16n8k16.row.col.f32.bf16.bf16.f32 "
        "{%0,%1,%2,%3}, {%4,%5,%6,%7}, {%8,%9}, {%0,%1,%2,%3};"
        : "+f"(d[0]), "+f"(d[1]), "+f"(d[2]), "+f"(d[3])
        : "r"(a[0]), "r"(a[1]), "r"(a[2]), "r"(a[3]), "r"(b[0]), "r"(b[1]));
}
__device__ __forceinline__ void mma16832_fp8(float* d, const uint32_t* a, const uint32_t* b) {
    asm volatile(
        "mma.sync.aligned.m16n8k32.row.col.f32.e4m3.e4m3.f32 "
        "{%0,%1,%2,%3}, {%4,%5,%6,%7}, {%8,%9}, {%0,%1,%2,%3};"
        : "+f"(d[0]), "+f"(d[1]), "+f"(d[2]), "+f"(d[3])
        : "r"(a[0]), "r"(a[1]), "r"(a[2]), "r"(a[3]), "r"(b[0]), "r"(b[1]));
}

__global__ __launch_bounds__(CTA, 2)
void ngp_fp8p_kernel(const float2* __restrict__ uv, const float* __restrict__ tables,
                     const float* __restrict__ w1, const float* __restrict__ b1,
                     const float* __restrict__ w2, const float* __restrict__ b2,
                     const float* __restrict__ w3, const float* __restrict__ b3,
                     float* __restrict__ out, int n)
{
    extern __shared__ char smem[];
    const int tid  = threadIdx.x;
    const int wid  = tid >> 5;
    const int lane = tid & 31;
    const int q    = lane >> 2;
    const int c    = lane & 3;

    // ---- stage weights once per persistent CTA ----
    // W1^T [n][k] bf16, pre-scaled by SC (folds fp8 scale into layer 1)
    for (int idx = tid; idx < 32 * 128; idx += CTA) {
        int j = idx >> 5, k = idx & 31;
        *(__nv_bfloat16*)(smem + OFF_W1T + j * W1S + k * 2) =
            __float2bfloat16(w1[k * 128 + j] * SC);
    }
    // W2^T [n][k_phys] e4m3 with k-PERMUTATION matching natural packed-D order:
    //   p = 16j + 4c + r  ->  logical col = 8*(2j + (r>>1)) + 2c + (r&1)
    for (int idx = tid; idx < 128 * 128; idx += CTA) {
        int jn = idx >> 7, p = idx & 127;
        int j  = p >> 4, rem = p & 15, cc = rem >> 2, rr = rem & 3;
        int kl = 8 * (2 * j + (rr >> 1)) + 2 * cc + (rr & 1);
        unsigned short pk = pack_e4m3x2(w2[kl * 128 + jn], 0.f);
        *(unsigned char*)(smem + OFF_W28 + jn * W2S8 + p) = (unsigned char)(pk & 0xFF);
    }
    float* sb1 = (float*)(smem + OFF_B1);
    float* sb2 = (float*)(smem + OFF_B2);
    float* sw3 = (float*)(smem + OFF_W3);
    float* sb3 = (float*)(smem + OFF_B3);
    for (int i = tid; i < 128; i += CTA) { sb1[i] = b1[i] * SC; sb2[i] = b2[i] * SC; }
    for (int i = tid; i < 384; i += CTA) sw3[i] = w3[i];
    if (tid < 3) sb3[tid] = b3[tid];
    __syncthreads();   // only CTA-wide sync; X is warp-private below

    const uint32_t sW1  = smem_u32(smem + OFF_W1T);
    const uint32_t sW28 = smem_u32(smem + OFF_W28);
    const uint32_t sX   = smem_u32(smem + OFF_X);
    char* Xbuf = smem + OFF_X;

    // ldmatrix lane-constant address parts (layout validated R5-R9)
    const int rA = wid * 16 + (lane & 7) + ((lane >> 3) & 1) * 8;
    const uint32_t offA   = (uint32_t)(rA * XS) + ((lane >> 4) * 16);
    const uint32_t offB1  = (uint32_t)((lane & 7) * W1S) + ((lane >> 3) * 16);
    const uint32_t offB28 = (uint32_t)((lane & 7) * W2S8) + ((lane >> 3) * 16);

    // corner-parallel encode: lane = 4*psub + corner
    const int corner = lane & 3;
    const int psub   = lane >> 2;
    const int ox     = corner >> 1;
    const int oy     = corner & 1;

    const int ntiles = (n + TILE - 1) / TILE;
    for (int t = blockIdx.x; t < ntiles; t += gridDim.x) {

        // ============ encode 16 points/warp: 2 groups of 8, 4 lanes/point ============
        __syncwarp();
#pragma unroll
        for (int g = 0; g < 2; g++) {
            const int pt  = wid * 16 + g * 8 + psub;
            const int gid = t * TILE + pt;
            const float2 p = __ldg(&uv[gid < n ? gid : (n - 1)]);
#pragma unroll
            for (int l = 0; l < NLEV; l++) {
                const unsigned res = 16u << l;
                float px = p.x * (float)res, py = p.y * (float)res;
                float fx = floorf(px), fy = floorf(py);
                float wx = px - fx, wy = py - fy;
                unsigned cx = (unsigned)(int)fx + (unsigned)ox;
                unsigned cy = (unsigned)(int)fy + (unsigned)oy;
                unsigned idx;
                if (res <= 512u)
                    idx = cx + cy * (res + 1u);
                else
                    idx = (cx ^ (cy * PRIME)) & TMASK;
                float2 f = __ldg((const float2*)tables + (size_t)l * TSZ + idx);
                float w = (ox ? wx : 1.f - wx) * (oy ? wy : 1.f - wy);
                float v0 = w * f.x, v1 = w * f.y;
                v0 += __shfl_xor_sync(0xffffffffu, v0, 1);
                v1 += __shfl_xor_sync(0xffffffffu, v1, 1);
                v0 += __shfl_xor_sync(0xffffffffu, v0, 2);
                v1 += __shfl_xor_sync(0xffffffffu, v1, 2);
                if (corner == 0)
                    *(uint32_t*)(Xbuf + pt * XS + l * 4) = pack_bf16x2(v0, v1);
            }
        }
        __syncwarp();

        // ====== layer 1 (bf16, pre-scaled): H -> fp8 A-fragments, NO repack ======
        uint32_t xa[2][4];
        ldm_x4(xa[0], sX + offA);
        ldm_x4(xa[1], sX + offA + 32);

        uint32_t ha8[4][4];          // layer-2 fp8 A fragments (4 k32-steps)
        unsigned short plo_prev = 0, phi_prev = 0;
#pragma unroll
        for (int s = 0; s < 4; s++) {
#pragma unroll
            for (int nt = 0; nt < 4; nt++) {
                const int b = 4 * s + nt;          // 8-col block index 0..15
                const int col0 = 8 * b;
                uint32_t bf[4];
                ldm_x4(bf, sW1 + (uint32_t)(col0 * W1S) + offB1);
                float d[4] = {0.f, 0.f, 0.f, 0.f};
                mma16816(d, xa[0], bf);
                mma16816(d, xa[1], bf + 2);
                float2 bb = *(const float2*)(sb1 + col0 + 2 * c);
                float h0 = fmaxf(d[0] + bb.x, 0.f);   // row q,   col 8b+2c  (already xSC)
                float h1 = fmaxf(d[1] + bb.y, 0.f);   // row q,   col 8b+2c+1
                float h2 = fmaxf(d[2] + bb.x, 0.f);   // row q+8, col 8b+2c
                float h3 = fmaxf(d[3] + bb.y, 0.f);   // row q+8, col 8b+2c+1
                unsigned short plo = pack_e4m3x2(h0, h1);
                unsigned short phi = pack_e4m3x2(h2, h3);
                if ((b & 1) == 0) {
                    plo_prev = plo; phi_prev = phi;
                } else {
                    // natural byte order == permuted W2 k order: direct concat
                    const int j = b >> 1, kk = j >> 1, half = j & 1;
                    ha8[kk][2 * half + 0] = (uint32_t)plo_prev | ((uint32_t)plo << 16); // row q
                    ha8[kk][2 * half + 1] = (uint32_t)phi_prev | ((uint32_t)phi << 16); // row q+8
                }
            }
        }

        // ===== layer 2 (fp8, k=32/mma) fused with layer 3 accumulation =====
        float o[6] = {};
#pragma unroll
        for (int s = 0; s < 4; s++) {
#pragma unroll
            for (int nt = 0; nt < 4; nt++) {
                const int col0 = s * 32 + nt * 8;
                float d[4] = {0.f, 0.f, 0.f, 0.f};
#pragma unroll
                for (int kk2 = 0; kk2 < 2; kk2++) {
                    uint32_t bf[4];
                    ldm_x4(bf, sW28 + (uint32_t)(col0 * W2S8) + kk2 * 64 + offB28);
                    mma16832_fp8(d, ha8[2 * kk2],     bf);
                    mma16832_fp8(d, ha8[2 * kk2 + 1], bf + 2);
                }
                float2 bb = *(const float2*)(sb2 + col0 + 2 * c);
                float h0 = fmaxf(d[0] + bb.x, 0.f);
                float h1 = fmaxf(d[1] + bb.y, 0.f);
                float h2 = fmaxf(d[2] + bb.x, 0.f);
                float h3 = fmaxf(d[3] + bb.y, 0.f);
                const float* w3a = sw3 + 3 * (col0 + 2 * c);
                const float* w3b = w3a + 3;
                o[0] = fmaf(h0, w3a[0], fmaf(h1, w3b[0], o[0]));
                o[1] = fmaf(h0, w3a[1], fmaf(h1, w3b[1], o[1]));
                o[2] = fmaf(h0, w3a[2], fmaf(h1, w3b[2], o[2]));
                o[3] = fmaf(h2, w3a[0], fmaf(h3, w3b[0], o[3]));
                o[4] = fmaf(h2, w3a[1], fmaf(h3, w3b[1], o[4]));
                o[5] = fmaf(h2, w3a[2], fmaf(h3, w3b[2], o[5]));
            }
        }

        // quad reduction, unscale, sigmoid, store
#pragma unroll
        for (int v = 0; v < 6; v++) {
            float x = o[v];
            x += __shfl_xor_sync(0xffffffffu, x, 1);
            x += __shfl_xor_sync(0xffffffffu, x, 2);
            o[v] = x * INV_SC;
        }

        if (c == 0) {
            int row0 = t * TILE + wid * 16 + q;
            int row1 = row0 + 8;
            if (row0 < n) {
                out[3 * row0 + 0] = 1.f / (1.f + __expf(-(o[0] + sb3[0])));
                out[3 * row0 + 1] = 1.f / (1.f + __expf(-(o[1] + sb3[1])));
                out[3 * row0 + 2] = 1.f / (1.f + __expf(-(o[2] + sb3[2])));
            }
            if (row1 < n) {
                out[3 * row1 + 0] = 1.f / (1.f + __expf(-(o[3] + sb3[0])));
                out[3 * row1 + 1] = 1.f / (1.f + __expf(-(o[4] + sb3[1])));
                out[3 * row1 + 2] = 1.f / (1.f + __expf(-(o[5] + sb3[2])));
            }
        }
    }
}

extern "C" void kernel_launch(void* const* d_in, const int* in_sizes, int n_in,
                              void* d_out, int out_size)
{
    const float2* uv     = (const float2*)d_in[0];
    const float*  tables = (const float*) d_in[1];
    const float*  w1     = (const float*) d_in[2];
    const float*  b1     = (const float*) d_in[3];
    const float*  w2     = (const float*) d_in[4];
    const float*  b2     = (const float*) d_in[5];
    const float*  w3     = (const float*) d_in[6];
    const float*  b3     = (const float*) d_in[7];
    float* out = (float*)d_out;

    int n = in_sizes[0] / 2;
    int ntiles = (n + TILE - 1) / TILE;

    cudaFuncSetAttribute(ngp_fp8p_kernel,
                         cudaFuncAttributeMaxDynamicSharedMemorySize, DSMEM);

    int grid = 304;                 // 2 persistent CTAs / SM
    if (grid > ntiles) grid = ntiles;

    ngp_fp8p_kernel<<<grid, CTA, DSMEM>>>(uv, tables, w1, b1, w2, b2, w3, b3, out, n);
}

// round 11
// speedup vs baseline: 1.3317x; 1.0652x over previous
#include <cuda_runtime.h>
#include <cuda_bf16.h>
#include <math.h>
#include <stdint.h>

#define NLEV   16
#define TBITS  20
#define TSZ    (1u << TBITS)
#define TMASK  (TSZ - 1u)
#define PRIME  2654435761u

#define CTA    256
#define TILE   128

#define W1S 80      // W1^T row stride (bytes): 32 bf16 padded to 80
#define W2S 272     // W2^T row stride: 128 bf16 padded to 272
#define XS  80      // X row stride: 32 bf16 padded to 80

#define OFF_W1T 0
#define OFF_W2T 10240
#define OFF_X   45056
#define OFF_B1  55296
#define OFF_B2  55808
#define OFF_W3  56320
#define OFF_B3  57856
#define DSMEM   57984

__device__ __forceinline__ uint32_t smem_u32(const void* p) {
    uint32_t a;
    asm("{ .reg .u64 t; cvta.to.shared.u64 t, %1; cvt.u32.u64 %0, t; }"
        : "=r"(a) : "l"(p));
    return a;
}
__device__ __forceinline__ uint32_t pack_bf16x2(float lo, float hi) {
    __nv_bfloat162 v = __float22bfloat162_rn(make_float2(lo, hi));
    return *(uint32_t*)&v;
}
__device__ __forceinline__ uint32_t hadd2_bf16(uint32_t a, uint32_t b) {
    uint32_t r;
    asm("add.rn.bf16x2 %0, %1, %2;" : "=r"(r) : "r"(a), "r"(b));
    return r;
}
__device__ __forceinline__ void ldm_x4(uint32_t* r, uint32_t addr) {
    asm volatile("ldmatrix.sync.aligned.m8n8.x4.shared.b16 {%0,%1,%2,%3}, [%4];"
                 : "=r"(r[0]), "=r"(r[1]), "=r"(r[2]), "=r"(r[3]) : "r"(addr));
}
__device__ __forceinline__ void mma16816(float* d, const uint32_t* a, const uint32_t* b) {
    asm volatile(
        "mma.sync.aligned.m16n8k16.row.col.f32.bf16.bf16.f32 "
        "{%0,%1,%2,%3}, {%4,%5,%6,%7}, {%8,%9}, {%0,%1,%2,%3};"
        : "+f"(d[0]), "+f"(d[1]), "+f"(d[2]), "+f"(d[3])
        : "r"(a[0]), "r"(a[1]), "r"(a[2]), "r"(a[3]), "r"(b[0]), "r"(b[1]));
}

__global__ __launch_bounds__(CTA, 2)
void ngp_mma5_kernel(const float2* __restrict__ uv, const float* __restrict__ tables,
                     const float* __restrict__ w1, const float* __restrict__ b1,
                     const float* __restrict__ w2, const float* __restrict__ b2,
                     const float* __restrict__ w3, const float* __restrict__ b3,
                     float* __restrict__ out, int n)
{
    extern __shared__ char smem[];
    const int tid  = threadIdx.x;
    const int wid  = tid >> 5;
    const int lane = tid & 31;
    const int q    = lane >> 2;
    const int c    = lane & 3;

    // ---- stage weights once per persistent CTA ----
    for (int idx = tid; idx < 32 * 128; idx += CTA) {     // W1^T [n=128][k=32]
        int j = idx >> 5, k = idx & 31;
        *(__nv_bfloat16*)(smem + OFF_W1T + j * W1S + k * 2) = __float2bfloat16(w1[k * 128 + j]);
    }
    for (int idx = tid; idx < 128 * 128; idx += CTA) {    // W2^T [n=128][k=128]
        int j = idx >> 7, k = idx & 127;
        *(__nv_bfloat16*)(smem + OFF_W2T + j * W2S + k * 2) = __float2bfloat16(w2[k * 128 + j]);
    }
    float* sb1 = (float*)(smem + OFF_B1);
    float* sb2 = (float*)(smem + OFF_B2);
    float* sw3 = (float*)(smem + OFF_W3);
    float* sb3 = (float*)(smem + OFF_B3);
    for (int i = tid; i < 128; i += CTA) { sb1[i] = b1[i]; sb2[i] = b2[i]; }
    for (int i = tid; i < 384; i += CTA) sw3[i] = w3[i];
    if (tid < 3) sb3[tid] = b3[tid];
    __syncthreads();       // the ONLY CTA-wide sync; X is warp-private below

    const uint32_t sW1 = smem_u32(smem + OFF_W1T);
    const uint32_t sW2 = smem_u32(smem + OFF_W2T);
    const uint32_t sX  = smem_u32(smem + OFF_X);
    char* Xbuf = smem + OFF_X;

    // ldmatrix lane-constant address parts (layout validated R5-R7)
    const int rA = wid * 16 + (lane & 7) + ((lane >> 3) & 1) * 8;
    const uint32_t offA  = (uint32_t)(rA * XS) + ((lane >> 4) * 16);
    const uint32_t offB1 = (uint32_t)((lane & 7) * W1S) + ((lane >> 3) * 16);
    const uint32_t offB2 = (uint32_t)((lane & 7) * W2S) + ((lane >> 3) * 16);

    // corner-parallel encode: lane = 4*psub + corner
    const int corner = lane & 3;
    const int psub   = lane >> 2;
    const int ox     = corner >> 1;
    const int oy     = corner & 1;

    const int ntiles = (n + TILE - 1) / TILE;
    for (int t = blockIdx.x; t < ntiles; t += gridDim.x) {

        // ============ encode 16 points/warp: 2 groups of 8, 4 lanes/point ============
        __syncwarp();
        {
            const int pt0  = wid * 16 + psub;
            const int gid0 = t * TILE + pt0;
            const int gid1 = gid0 + 8;
            const float2 pA = __ldg(&uv[gid0 < n ? gid0 : (n - 1)]);
            const float2 pB = __ldg(&uv[gid1 < n ? gid1 : (n - 1)]);
#pragma unroll
            for (int g = 0; g < 2; g++) {
                const float2 p = g ? pB : pA;
                const int pt = pt0 + g * 8;
                uint32_t prev = 0;
#pragma unroll
                for (int l = 0; l < NLEV; l++) {
                    const unsigned res = 16u << l;
                    float px = p.x * (float)res, py = p.y * (float)res;
                    float fx = floorf(px), fy = floorf(py);
                    float wx = px - fx, wy = py - fy;
                    unsigned cx = (unsigned)(int)fx + (unsigned)ox;
                    unsigned cy = (unsigned)(int)fy + (unsigned)oy;
                    unsigned idx;
                    if (res <= 512u)
                        idx = cx + cy * (res + 1u);
                    else
                        idx = (cx ^ (cy * PRIME)) & TMASK;
                    float2 f = __ldg((const float2*)tables + (size_t)l * TSZ + idx);
                    float w = (ox ? wx : 1.f - wx) * (oy ? wy : 1.f - wy);
                    // pack corner partial to bf16x2, reduce over 4 corner lanes with HADD2
                    uint32_t u = pack_bf16x2(w * f.x, w * f.y);
                    u = hadd2_bf16(u, __shfl_xor_sync(0xffffffffu, u, 1));
                    u = hadd2_bf16(u, __shfl_xor_sync(0xffffffffu, u, 2));
                    if ((l & 1) == 0) {
                        prev = u;
                    } else if (corner == 0) {
                        *(uint2*)(Xbuf + pt * XS + (l - 1) * 4) = make_uint2(prev, u);
                    }
                }
            }
        }
        __syncwarp();

        // ================= layer 1: 16 rows/warp, H -> registers =================
        uint32_t xa[2][4];
        ldm_x4(xa[0], sX + offA);
        ldm_x4(xa[1], sX + offA + 32);

        uint32_t ha[8][4];
#pragma unroll
        for (int s = 0; s < 4; s++) {
#pragma unroll
            for (int nt = 0; nt < 4; nt++) {
                const int col0 = s * 32 + nt * 8;
                uint32_t bf[4];
                ldm_x4(bf, sW1 + (uint32_t)(col0 * W1S) + offB1);
                float d[4] = {0.f, 0.f, 0.f, 0.f};
                mma16816(d, xa[0], bf);
                mma16816(d, xa[1], bf + 2);
                float2 bb = *(const float2*)(sb1 + col0 + 2 * c);
                float h0 = fmaxf(d[0] + bb.x, 0.f);
                float h1 = fmaxf(d[1] + bb.y, 0.f);
                float h2 = fmaxf(d[2] + bb.x, 0.f);
                float h3 = fmaxf(d[3] + bb.y, 0.f);
                const int K = 2 * s + (nt >> 1);
                if (nt & 1) { ha[K][2] = pack_bf16x2(h0, h1); ha[K][3] = pack_bf16x2(h2, h3); }
                else        { ha[K][0] = pack_bf16x2(h0, h1); ha[K][1] = pack_bf16x2(h2, h3); }
            }
        }

        // ============ layer 2 (H @ W2) fused with layer 3 accumulation ============
        float oA0 = 0.f, oA1 = 0.f, oA2 = 0.f;
        float oB0 = 0.f, oB1 = 0.f, oB2 = 0.f;
#pragma unroll
        for (int s = 0; s < 4; s++) {
#pragma unroll
            for (int nt = 0; nt < 4; nt++) {
                const int col0 = s * 32 + nt * 8;
                float d[4] = {0.f, 0.f, 0.f, 0.f};
#pragma unroll
                for (int ktp = 0; ktp < 4; ktp++) {
                    uint32_t bf[4];
                    ldm_x4(bf, sW2 + (uint32_t)(col0 * W2S) + ktp * 64 + offB2);
                    mma16816(d, ha[2 * ktp],     bf);
                    mma16816(d, ha[2 * ktp + 1], bf + 2);
                }
                float2 bb = *(const float2*)(sb2 + col0 + 2 * c);
                float h0 = fmaxf(d[0] + bb.x, 0.f);
                float h1 = fmaxf(d[1] + bb.y, 0.f);
                float h2 = fmaxf(d[2] + bb.x, 0.f);
                float h3 = fmaxf(d[3] + bb.y, 0.f);
                const float* w3a = sw3 + 3 * (col0 + 2 * c);
                const float* w3b = w3a + 3;
                oA0 = fmaf(h0, w3a[0], fmaf(h1, w3b[0], oA0));
                oA1 = fmaf(h0, w3a[1], fmaf(h1, w3b[1], oA1));
                oA2 = fmaf(h0, w3a[2], fmaf(h1, w3b[2], oA2));
                oB0 = fmaf(h2, w3a[0], fmaf(h3, w3b[0], oB0));
                oB1 = fmaf(h2, w3a[1], fmaf(h3, w3b[1], oB1));
                oB2 = fmaf(h2, w3a[2], fmaf(h3, w3b[2], oB2));
            }
        }

#pragma unroll
        for (int m = 1; m <= 2; m <<= 1) {
            oA0 += __shfl_xor_sync(0xffffffffu, oA0, m);
            oA1 += __shfl_xor_sync(0xffffffffu, oA1, m);
            oA2 += __shfl_xor_sync(0xffffffffu, oA2, m);
            oB0 += __shfl_xor_sync(0xffffffffu, oB0, m);
            oB1 += __shfl_xor_sync(0xffffffffu, oB1, m);
            oB2 += __shfl_xor_sync(0xffffffffu, oB2, m);
        }

        if (c == 0) {
            int row0 = t * TILE + wid * 16 + q;
            int row1 = row0 + 8;
            if (row0 < n) {
                out[3 * row0 + 0] = 1.f / (1.f + __expf(-(oA0 + sb3[0])));
                out[3 * row0 + 1] = 1.f / (1.f + __expf(-(oA1 + sb3[1])));
                out[3 * row0 + 2] = 1.f / (1.f + __expf(-(oA2 + sb3[2])));
            }
            if (row1 < n) {
                out[3 * row1 + 0] = 1.f / (1.f + __expf(-(oB0 + sb3[0])));
                out[3 * row1 + 1] = 1.f / (1.f + __expf(-(oB1 + sb3[1])));
                out[3 * row1 + 2] = 1.f / (1.f + __expf(-(oB2 + sb3[2])));
            }
        }
    }
}

extern "C" void kernel_launch(void* const* d_in, const int* in_sizes, int n_in,
                              void* d_out, int out_size)
{
    const float2* uv     = (const float2*)d_in[0];
    const float*  tables = (const float*) d_in[1];
    const float*  w1     = (const float*) d_in[2];
    const float*  b1     = (const float*) d_in[3];
    const float*  w2     = (const float*) d_in[4];
    const float*  b2     = (const float*) d_in[5];
    const float*  w3     = (const float*) d_in[6];
    const float*  b3     = (const float*) d_in[7];
    float* out = (float*)d_out;

    int n = in_sizes[0] / 2;
    int ntiles = (n + TILE - 1) / TILE;

    cudaFuncSetAttribute(ngp_mma5_kernel,
                         cudaFuncAttributeMaxDynamicSharedMemorySize, DSMEM);

    int grid = 304;                 // 2 persistent CTAs / SM
    if (grid > ntiles) grid = ntiles;

    ngp_mma5_kernel<<<grid, CTA, DSMEM>>>(uv, tables, w1, b1, w2, b2, w3, b3, out, n);
}